// round 9
// baseline (speedup 1.0000x reference)
#include <cuda_runtime.h>

// VDEncoderDecoder: stacked LSTM encoder (8->32->8->1, T=48) + decoder
// (1->2->2->1, 60 steps) + fused fc via g = fc2_w @ fc1_w.
// One thread per batch element. Key change vs R8: the big-layer weights
// (e1/e2 ih+hh, 26 KB) live in __constant__ memory, read via the dedicated
// constant port (warp-uniform addresses) -> shared/L1 wavefront traffic,
// the measured binding resource (69% busy), drops to near zero.

#define TPB 32
static constexpr int BATCH = 32768;
static constexpr int T = 48;

// constant-memory weight blocks (float4 granularity; row-major identical to inputs)
static constexpr int C_W1IH4 = 0;     // 256  float4: [row 0..127][d 0..1]
static constexpr int C_W1HH4 = 256;   // 1024 float4: [row 0..127][j 0..7]
static constexpr int C_W2IH4 = 1280;  // 256  float4: [row 0..31][d 0..7]
static constexpr int C_W2HH4 = 1536;  // 64   float4: [row 0..31][j 0..1]
static constexpr int C_TOTAL4 = 1600;

__constant__ __align__(16) float4 CW4[C_TOTAL4];
__constant__ float CBIAS[160];   // b1[128] then b2[32]

// shared-memory float offsets (small layers + fused fc only)
static constexpr int OFF_W3IH = 0;    // 32
static constexpr int OFF_W3HH = 32;   // 4
static constexpr int OFF_B3   = 36;   // 4
static constexpr int OFF_D1IH = 40;   // 8
static constexpr int OFF_D1HH = 48;   // 16
static constexpr int OFF_BD1  = 64;   // 8
static constexpr int OFF_D2IH = 72;   // 16
static constexpr int OFF_D2HH = 88;   // 16
static constexpr int OFF_BD2  = 104;  // 8
static constexpr int OFF_D3IH = 112;  // 8
static constexpr int OFF_D3HH = 120;  // 4
static constexpr int OFF_BD3  = 124;  // 4
static constexpr int OFF_G    = 128;  // 720: g[t*12+j] = fc2 @ fc1
static constexpr int OFF_CB   = 848;  // 12
static constexpr int SMEM_FLOATS = 860;

__device__ __forceinline__ float sigf(float x) {
    return __fdividef(1.0f, 1.0f + __expf(-x));
}
__device__ __forceinline__ float tanhx(float x) {
    float e = __expf(2.0f * x);
    return 1.0f - __fdividef(2.0f, e + 1.0f);
}

// e1 cell: H=32, DIN=8, weights in constant memory (direct-name indexing so
// nvcc emits ld.const.v4).
__device__ __forceinline__ void lstm_e1(const float (&xin)[8], float (&h)[32], float* __restrict__ c)
{
    float hn[32];
#pragma unroll 1
    for (int u = 0; u < 32; ++u) {
        float a0 = CBIAS[u];
        float a1 = CBIAS[32 + u];
        float a2 = CBIAS[64 + u];
        float a3 = CBIAS[96 + u];
#pragma unroll
        for (int d = 0; d < 2; ++d) {
            float4 q0 = CW4[C_W1IH4 + u * 2 + d];
            float4 q1 = CW4[C_W1IH4 + (32 + u) * 2 + d];
            float4 q2 = CW4[C_W1IH4 + (64 + u) * 2 + d];
            float4 q3 = CW4[C_W1IH4 + (96 + u) * 2 + d];
            float x0 = xin[4 * d + 0], x1 = xin[4 * d + 1];
            float x2 = xin[4 * d + 2], x3 = xin[4 * d + 3];
            a0 = fmaf(x0, q0.x, a0); a1 = fmaf(x0, q1.x, a1);
            a2 = fmaf(x0, q2.x, a2); a3 = fmaf(x0, q3.x, a3);
            a0 = fmaf(x1, q0.y, a0); a1 = fmaf(x1, q1.y, a1);
            a2 = fmaf(x1, q2.y, a2); a3 = fmaf(x1, q3.y, a3);
            a0 = fmaf(x2, q0.z, a0); a1 = fmaf(x2, q1.z, a1);
            a2 = fmaf(x2, q2.z, a2); a3 = fmaf(x2, q3.z, a3);
            a0 = fmaf(x3, q0.w, a0); a1 = fmaf(x3, q1.w, a1);
            a2 = fmaf(x3, q2.w, a2); a3 = fmaf(x3, q3.w, a3);
        }
#pragma unroll
        for (int j = 0; j < 8; ++j) {
            float4 q0 = CW4[C_W1HH4 + u * 8 + j];
            float4 q1 = CW4[C_W1HH4 + (32 + u) * 8 + j];
            float4 q2 = CW4[C_W1HH4 + (64 + u) * 8 + j];
            float4 q3 = CW4[C_W1HH4 + (96 + u) * 8 + j];
            float h0 = h[4 * j + 0], h1v = h[4 * j + 1];
            float h2v = h[4 * j + 2], h3v = h[4 * j + 3];
            a0 = fmaf(h0, q0.x, a0); a1 = fmaf(h0, q1.x, a1);
            a2 = fmaf(h0, q2.x, a2); a3 = fmaf(h0, q3.x, a3);
            a0 = fmaf(h1v, q0.y, a0); a1 = fmaf(h1v, q1.y, a1);
            a2 = fmaf(h1v, q2.y, a2); a3 = fmaf(h1v, q3.y, a3);
            a0 = fmaf(h2v, q0.z, a0); a1 = fmaf(h2v, q1.z, a1);
            a2 = fmaf(h2v, q2.z, a2); a3 = fmaf(h2v, q3.z, a3);
            a0 = fmaf(h3v, q0.w, a0); a1 = fmaf(h3v, q1.w, a1);
            a2 = fmaf(h3v, q2.w, a2); a3 = fmaf(h3v, q3.w, a3);
        }
        float ig = sigf(a0);
        float fg = sigf(a1);
        float gg = tanhx(a2);
        float og = sigf(a3);
        float cn = fmaf(fg, c[u], ig * gg);
        c[u] = cn;
        hn[u] = og * tanhx(cn);
    }
#pragma unroll
    for (int u = 0; u < 32; ++u) h[u] = hn[u];
}

// e2 cell: H=8, DIN=32, weights in constant memory.
__device__ __forceinline__ void lstm_e2(const float (&xin)[32], float (&h)[8], float* __restrict__ c)
{
    float hn[8];
#pragma unroll 1
    for (int u = 0; u < 8; ++u) {
        float a0 = CBIAS[128 + u];
        float a1 = CBIAS[128 + 8 + u];
        float a2 = CBIAS[128 + 16 + u];
        float a3 = CBIAS[128 + 24 + u];
#pragma unroll
        for (int d = 0; d < 8; ++d) {
            float4 q0 = CW4[C_W2IH4 + u * 8 + d];
            float4 q1 = CW4[C_W2IH4 + (8 + u) * 8 + d];
            float4 q2 = CW4[C_W2IH4 + (16 + u) * 8 + d];
            float4 q3 = CW4[C_W2IH4 + (24 + u) * 8 + d];
            float x0 = xin[4 * d + 0], x1 = xin[4 * d + 1];
            float x2 = xin[4 * d + 2], x3 = xin[4 * d + 3];
            a0 = fmaf(x0, q0.x, a0); a1 = fmaf(x0, q1.x, a1);
            a2 = fmaf(x0, q2.x, a2); a3 = fmaf(x0, q3.x, a3);
            a0 = fmaf(x1, q0.y, a0); a1 = fmaf(x1, q1.y, a1);
            a2 = fmaf(x1, q2.y, a2); a3 = fmaf(x1, q3.y, a3);
            a0 = fmaf(x2, q0.z, a0); a1 = fmaf(x2, q1.z, a1);
            a2 = fmaf(x2, q2.z, a2); a3 = fmaf(x2, q3.z, a3);
            a0 = fmaf(x3, q0.w, a0); a1 = fmaf(x3, q1.w, a1);
            a2 = fmaf(x3, q2.w, a2); a3 = fmaf(x3, q3.w, a3);
        }
#pragma unroll
        for (int j = 0; j < 2; ++j) {
            float4 q0 = CW4[C_W2HH4 + u * 2 + j];
            float4 q1 = CW4[C_W2HH4 + (8 + u) * 2 + j];
            float4 q2 = CW4[C_W2HH4 + (16 + u) * 2 + j];
            float4 q3 = CW4[C_W2HH4 + (24 + u) * 2 + j];
            float h0 = h[4 * j + 0], h1v = h[4 * j + 1];
            float h2v = h[4 * j + 2], h3v = h[4 * j + 3];
            a0 = fmaf(h0, q0.x, a0); a1 = fmaf(h0, q1.x, a1);
            a2 = fmaf(h0, q2.x, a2); a3 = fmaf(h0, q3.x, a3);
            a0 = fmaf(h1v, q0.y, a0); a1 = fmaf(h1v, q1.y, a1);
            a2 = fmaf(h1v, q2.y, a2); a3 = fmaf(h1v, q3.y, a3);
            a0 = fmaf(h2v, q0.z, a0); a1 = fmaf(h2v, q1.z, a1);
            a2 = fmaf(h2v, q2.z, a2); a3 = fmaf(h2v, q3.z, a3);
            a0 = fmaf(h3v, q0.w, a0); a1 = fmaf(h3v, q1.w, a1);
            a2 = fmaf(h3v, q2.w, a2); a3 = fmaf(h3v, q3.w, a3);
        }
        float ig = sigf(a0);
        float fg = sigf(a1);
        float gg = tanhx(a2);
        float og = sigf(a3);
        float cn = fmaf(fg, c[u], ig * gg);
        c[u] = cn;
        hn[u] = og * tanhx(cn);
    }
#pragma unroll
    for (int u = 0; u < 8; ++u) h[u] = hn[u];
}

// Small scalar LSTM cell (smem weights), fully unrolled.
template<int H, int DIN>
__device__ __forceinline__ void lstm_small(
    const float* __restrict__ wih, const float* __restrict__ whh,
    const float* __restrict__ bias,
    const float (&xin)[DIN], float (&h)[H], float (&c)[H])
{
    float hn[H];
#pragma unroll
    for (int u = 0; u < H; ++u) {
        float a0 = bias[u];
        float a1 = bias[H + u];
        float a2 = bias[2 * H + u];
        float a3 = bias[3 * H + u];
#pragma unroll
        for (int d = 0; d < DIN; ++d) {
            float xv = xin[d];
            a0 = fmaf(xv, wih[u * DIN + d], a0);
            a1 = fmaf(xv, wih[(H + u) * DIN + d], a1);
            a2 = fmaf(xv, wih[(2 * H + u) * DIN + d], a2);
            a3 = fmaf(xv, wih[(3 * H + u) * DIN + d], a3);
        }
#pragma unroll
        for (int j = 0; j < H; ++j) {
            float hv = h[j];
            a0 = fmaf(hv, whh[u * H + j], a0);
            a1 = fmaf(hv, whh[(H + u) * H + j], a1);
            a2 = fmaf(hv, whh[(2 * H + u) * H + j], a2);
            a3 = fmaf(hv, whh[(3 * H + u) * H + j], a3);
        }
        float ig = sigf(a0);
        float fg = sigf(a1);
        float gg = tanhx(a2);
        float og = sigf(a3);
        float cn = fmaf(fg, c[u], ig * gg);
        c[u] = cn;
        hn[u] = og * tanhx(cn);
    }
#pragma unroll
    for (int u = 0; u < H; ++u) h[u] = hn[u];
}

__global__ void __launch_bounds__(TPB)
vd_encdec_kernel(
    const float* __restrict__ x,
    const float* __restrict__ w3ih, const float* __restrict__ w3hh, const float* __restrict__ b3,
    const float* __restrict__ d1ih, const float* __restrict__ d1hh, const float* __restrict__ bd1,
    const float* __restrict__ d2ih, const float* __restrict__ d2hh, const float* __restrict__ bd2,
    const float* __restrict__ d3ih, const float* __restrict__ d3hh, const float* __restrict__ bd3,
    const float* __restrict__ fc1w, const float* __restrict__ fc1b,
    const float* __restrict__ fc2w, const float* __restrict__ fc2b,
    float* __restrict__ out)
{
    __shared__ __align__(16) float sw[SMEM_FLOATS];
    const int tid = threadIdx.x;

    for (int i = tid; i < 32; i += TPB) sw[OFF_W3IH + i] = w3ih[i];
    if (tid < 4)  sw[OFF_W3HH + tid] = w3hh[tid];
    if (tid < 4)  sw[OFF_B3   + tid] = b3[tid];
    if (tid < 8)  sw[OFF_D1IH + tid] = d1ih[tid];
    if (tid < 16) sw[OFF_D1HH + tid] = d1hh[tid];
    if (tid < 8)  sw[OFF_BD1 + tid] = bd1[tid];
    if (tid < 16) sw[OFF_D2IH + tid] = d2ih[tid];
    if (tid < 16) sw[OFF_D2HH + tid] = d2hh[tid];
    if (tid < 8)  sw[OFF_BD2 + tid] = bd2[tid];
    if (tid < 8)  sw[OFF_D3IH + tid] = d3ih[tid];
    if (tid < 4)  sw[OFF_D3HH + tid] = d3hh[tid];
    if (tid < 4)  sw[OFF_BD3 + tid] = bd3[tid];
    // fused fc: g[t*12+j] = sum_k fc2w[j,k] * fc1w[k,t]
    for (int i = tid; i < 720; i += TPB) {
        int t = i / 12, j = i % 12;
        float a = 0.0f;
        for (int k = 0; k < 32; ++k)
            a = fmaf(fc2w[j * 32 + k], fc1w[k * 60 + t], a);
        sw[OFF_G + i] = a;
    }
    if (tid < 12) {
        float a = fc2b[tid];
        for (int k = 0; k < 32; ++k)
            a = fmaf(fc2w[tid * 32 + k], fc1b[k], a);
        sw[OFF_CB + tid] = a;
    }
    __syncthreads();

    const int b = blockIdx.x * TPB + tid;
    const float* xb = x + (size_t)b * (T * 8);

    float h1[32], c1[32], h2[8], c2[8], h3[1], c3[1];
    float hd1[2], cd1[2], hd2[2], cd2[2], hd3[1], cd3[1];
    float acc[12];
#pragma unroll
    for (int i = 0; i < 32; ++i) { h1[i] = 0.0f; c1[i] = 0.0f; }
#pragma unroll
    for (int i = 0; i < 8; ++i) { h2[i] = 0.0f; c2[i] = 0.0f; }
    h3[0] = 0.0f; c3[0] = 0.0f;
#pragma unroll
    for (int i = 0; i < 2; ++i) { hd1[i] = 0.0f; cd1[i] = 0.0f; hd2[i] = 0.0f; cd2[i] = 0.0f; }
    hd3[0] = 0.0f; cd3[0] = 0.0f;
#pragma unroll
    for (int i = 0; i < 12; ++i) acc[i] = 0.0f;

    // ---- fused steps t = 0..47 ----
#pragma unroll 1
    for (int t = 0; t < T; ++t) {
        float4 xa = *reinterpret_cast<const float4*>(xb + t * 8);
        float4 xc = *reinterpret_cast<const float4*>(xb + t * 8 + 4);
        float xr[8] = { xa.x, xa.y, xa.z, xa.w, xc.x, xc.y, xc.z, xc.w };

        lstm_e1(xr, h1, c1);
        lstm_e2(h1, h2, c2);
        lstm_small<1, 8>(sw + OFF_W3IH, sw + OFF_W3HH, sw + OFF_B3, h2, h3, c3);

        float dv[1] = { h3[0] };
        lstm_small<2, 1>(sw + OFF_D1IH, sw + OFF_D1HH, sw + OFF_BD1, dv, hd1, cd1);
        lstm_small<2, 2>(sw + OFF_D2IH, sw + OFF_D2HH, sw + OFF_BD2, hd1, hd2, cd2);
        lstm_small<1, 2>(sw + OFF_D3IH, sw + OFF_D3HH, sw + OFF_BD3, hd2, hd3, cd3);

        float y = hd3[0];
        const float* gr = sw + OFF_G + t * 12;
#pragma unroll
        for (int j = 0; j < 12; ++j) acc[j] = fmaf(y, gr[j], acc[j]);
    }

    // ---- aux steps t = 48..59: decoder input = x[b, t-12, 4] ----
#pragma unroll 1
    for (int t = T; t < 60; ++t) {
        float dv[1] = { xb[(t - 12) * 8 + 4] };
        lstm_small<2, 1>(sw + OFF_D1IH, sw + OFF_D1HH, sw + OFF_BD1, dv, hd1, cd1);
        lstm_small<2, 2>(sw + OFF_D2IH, sw + OFF_D2HH, sw + OFF_BD2, hd1, hd2, cd2);
        lstm_small<1, 2>(sw + OFF_D3IH, sw + OFF_D3HH, sw + OFF_BD3, hd2, hd3, cd3);

        float y = hd3[0];
        const float* gr = sw + OFF_G + t * 12;
#pragma unroll
        for (int j = 0; j < 12; ++j) acc[j] = fmaf(y, gr[j], acc[j]);
    }

    // ---- epilogue ----
    float r[12];
#pragma unroll
    for (int j = 0; j < 12; ++j) r[j] = acc[j] + sw[OFF_CB + j];
    float4* op = reinterpret_cast<float4*>(out + (size_t)b * 12);
    op[0] = make_float4(r[0], r[1], r[2], r[3]);
    op[1] = make_float4(r[4], r[5], r[6], r[7]);
    op[2] = make_float4(r[8], r[9], r[10], r[11]);
}

extern "C" void kernel_launch(void* const* d_in, const int* in_sizes, int n_in,
                              void* d_out, int out_size) {
    (void)in_sizes; (void)n_in; (void)out_size;
    const float* x    = (const float*)d_in[0];
    const float* w1ih = (const float*)d_in[1];
    const float* w1hh = (const float*)d_in[2];
    const float* b1   = (const float*)d_in[3];
    const float* w2ih = (const float*)d_in[4];
    const float* w2hh = (const float*)d_in[5];
    const float* b2   = (const float*)d_in[6];
    const float* w3ih = (const float*)d_in[7];
    const float* w3hh = (const float*)d_in[8];
    const float* b3   = (const float*)d_in[9];
    const float* d1ih = (const float*)d_in[10];
    const float* d1hh = (const float*)d_in[11];
    const float* bd1  = (const float*)d_in[12];
    const float* d2ih = (const float*)d_in[13];
    const float* d2hh = (const float*)d_in[14];
    const float* bd2  = (const float*)d_in[15];
    const float* d3ih = (const float*)d_in[16];
    const float* d3hh = (const float*)d_in[17];
    const float* bd3  = (const float*)d_in[18];
    const float* fc1w = (const float*)d_in[19];
    const float* fc1b = (const float*)d_in[20];
    const float* fc2w = (const float*)d_in[21];
    const float* fc2b = (const float*)d_in[22];
    float* out = (float*)d_out;

    // Stage big-layer weights into constant memory (D2D async memcpys,
    // graph-capturable, deterministic, no allocation).
    cudaMemcpyToSymbolAsync(CW4, w1ih, 1024 * 4, (size_t)C_W1IH4 * 16, cudaMemcpyDeviceToDevice, 0);
    cudaMemcpyToSymbolAsync(CW4, w1hh, 4096 * 4, (size_t)C_W1HH4 * 16, cudaMemcpyDeviceToDevice, 0);
    cudaMemcpyToSymbolAsync(CW4, w2ih, 1024 * 4, (size_t)C_W2IH4 * 16, cudaMemcpyDeviceToDevice, 0);
    cudaMemcpyToSymbolAsync(CW4, w2hh, 256 * 4,  (size_t)C_W2HH4 * 16, cudaMemcpyDeviceToDevice, 0);
    cudaMemcpyToSymbolAsync(CBIAS, b1, 128 * 4, 0, cudaMemcpyDeviceToDevice, 0);
    cudaMemcpyToSymbolAsync(CBIAS, b2, 32 * 4, 128 * 4, cudaMemcpyDeviceToDevice, 0);

    dim3 grid(BATCH / TPB);
    dim3 block(TPB);
    vd_encdec_kernel<<<grid, block>>>(
        x, w3ih, w3hh, b3,
        d1ih, d1hh, bd1, d2ih, d2hh, bd2, d3ih, d3hh, bd3,
        fc1w, fc1b, fc2w, fc2b, out);
}

// round 10
// speedup vs baseline: 1.1784x; 1.1784x over previous
#include <cuda_runtime.h>

// VDEncoderDecoder: stacked LSTM encoder (8->32->8->1, T=48) + decoder
// (1->2->2->1, 60 steps) + fused fc via g = fc2_w @ fc1_w.
// One thread per batch element. Weight traffic SPLIT across the two
// independent on-chip ports (measured: const port ~4.25 cyc/warp-LDC.128/SM,
// smem crossbar ~4.0 cyc/warp-LDS.128/SM, fully parallel):
//   const: e1 W_hh gates i,f + e2 W_ih + biases   (768 float4/thread/t)
//   smem : e1 W_ih + e1 W_hh gates g,o + e2 W_hh  (832 float4/thread/t)
// Both ports + FMA pipe balance at ~23k cyc/SM/timestep.

#define TPB 32
static constexpr int BATCH = 32768;
static constexpr int T = 48;

// constant memory: e1 hh gates i,f (rows 0..63 of w1hh) and full e2 ih
__constant__ __align__(16) float4 C_E1HH_IF[512];  // (g*32+u)*8 + j, g in {0,1}
__constant__ __align__(16) float4 C_E2IH[256];     // (g*8+u)*8 + d, g in {0..3}
__constant__ float CB1[128];
__constant__ float CB2[32];

// shared-memory float offsets
static constexpr int OFF_W1IH  = 0;     // 128x8 = 1024
static constexpr int OFF_W1HGO = 1024;  // rows 64..127 of w1hh: 64x32 = 2048
static constexpr int OFF_W2HH  = 3072;  // 32x8 = 256
static constexpr int OFF_W3IH  = 3328;  // 32
static constexpr int OFF_W3HH  = 3360;  // 4
static constexpr int OFF_B3    = 3364;  // 4
static constexpr int OFF_D1IH  = 3368;  // 8
static constexpr int OFF_D1HH  = 3376;  // 16
static constexpr int OFF_BD1   = 3392;  // 8
static constexpr int OFF_D2IH  = 3400;  // 16
static constexpr int OFF_D2HH  = 3416;  // 16
static constexpr int OFF_BD2   = 3432;  // 8
static constexpr int OFF_D3IH  = 3440;  // 8
static constexpr int OFF_D3HH  = 3448;  // 4
static constexpr int OFF_BD3   = 3452;  // 4
static constexpr int OFF_G     = 3456;  // 720
static constexpr int OFF_CB    = 4176;  // 12
static constexpr int SMEM_FLOATS = 4188; // ~16.8 KB

__device__ __forceinline__ float sigf(float x) {
    return __fdividef(1.0f, 1.0f + __expf(-x));
}
__device__ __forceinline__ float tanhx(float x) {
    float e = __expf(2.0f * x);
    return 1.0f - __fdividef(2.0f, e + 1.0f);
}

// e1: H=32, DIN=8. ih + hh(g,o) from smem; hh(i,f) + bias from const.
__device__ __forceinline__ void lstm_e1(
    const float* __restrict__ swih, const float* __restrict__ swhh_go,
    const float (&xin)[8], float (&h)[32], float* __restrict__ c)
{
    float hn[32];
#pragma unroll 1
    for (int u = 0; u < 32; ++u) {
        float a0 = CB1[u];
        float a1 = CB1[32 + u];
        float a2 = CB1[64 + u];
        float a3 = CB1[96 + u];
        const float4* w0 = reinterpret_cast<const float4*>(swih + u * 8);
        const float4* w1 = reinterpret_cast<const float4*>(swih + (32 + u) * 8);
        const float4* w2 = reinterpret_cast<const float4*>(swih + (64 + u) * 8);
        const float4* w3 = reinterpret_cast<const float4*>(swih + (96 + u) * 8);
#pragma unroll
        for (int d = 0; d < 2; ++d) {
            float4 q0 = w0[d], q1 = w1[d], q2 = w2[d], q3 = w3[d];
            float x0 = xin[4 * d + 0], x1 = xin[4 * d + 1];
            float x2 = xin[4 * d + 2], x3 = xin[4 * d + 3];
            a0 = fmaf(x0, q0.x, a0); a1 = fmaf(x0, q1.x, a1);
            a2 = fmaf(x0, q2.x, a2); a3 = fmaf(x0, q3.x, a3);
            a0 = fmaf(x1, q0.y, a0); a1 = fmaf(x1, q1.y, a1);
            a2 = fmaf(x1, q2.y, a2); a3 = fmaf(x1, q3.y, a3);
            a0 = fmaf(x2, q0.z, a0); a1 = fmaf(x2, q1.z, a1);
            a2 = fmaf(x2, q2.z, a2); a3 = fmaf(x2, q3.z, a3);
            a0 = fmaf(x3, q0.w, a0); a1 = fmaf(x3, q1.w, a1);
            a2 = fmaf(x3, q2.w, a2); a3 = fmaf(x3, q3.w, a3);
        }
        const float4* vg = reinterpret_cast<const float4*>(swhh_go + u * 32);
        const float4* vo = reinterpret_cast<const float4*>(swhh_go + (32 + u) * 32);
#pragma unroll
        for (int j = 0; j < 8; ++j) {
            float4 qi = C_E1HH_IF[u * 8 + j];          // gate i  (const port)
            float4 qf = C_E1HH_IF[(32 + u) * 8 + j];   // gate f  (const port)
            float4 qg = vg[j];                          // gate g  (smem port)
            float4 qo = vo[j];                          // gate o  (smem port)
            float h0 = h[4 * j + 0], h1v = h[4 * j + 1];
            float h2v = h[4 * j + 2], h3v = h[4 * j + 3];
            a0 = fmaf(h0, qi.x, a0);  a1 = fmaf(h0, qf.x, a1);
            a2 = fmaf(h0, qg.x, a2);  a3 = fmaf(h0, qo.x, a3);
            a0 = fmaf(h1v, qi.y, a0); a1 = fmaf(h1v, qf.y, a1);
            a2 = fmaf(h1v, qg.y, a2); a3 = fmaf(h1v, qo.y, a3);
            a0 = fmaf(h2v, qi.z, a0); a1 = fmaf(h2v, qf.z, a1);
            a2 = fmaf(h2v, qg.z, a2); a3 = fmaf(h2v, qo.z, a3);
            a0 = fmaf(h3v, qi.w, a0); a1 = fmaf(h3v, qf.w, a1);
            a2 = fmaf(h3v, qg.w, a2); a3 = fmaf(h3v, qo.w, a3);
        }
        float ig = sigf(a0);
        float fg = sigf(a1);
        float gg = tanhx(a2);
        float og = sigf(a3);
        float cn = fmaf(fg, c[u], ig * gg);
        c[u] = cn;
        hn[u] = og * tanhx(cn);
    }
#pragma unroll
    for (int u = 0; u < 32; ++u) h[u] = hn[u];
}

// e2: H=8, DIN=32. ih from const; hh from smem.
__device__ __forceinline__ void lstm_e2(
    const float* __restrict__ swhh,
    const float (&xin)[32], float (&h)[8], float* __restrict__ c)
{
    float hn[8];
#pragma unroll 1
    for (int u = 0; u < 8; ++u) {
        float a0 = CB2[u];
        float a1 = CB2[8 + u];
        float a2 = CB2[16 + u];
        float a3 = CB2[24 + u];
#pragma unroll
        for (int d = 0; d < 8; ++d) {
            float4 q0 = C_E2IH[u * 8 + d];
            float4 q1 = C_E2IH[(8 + u) * 8 + d];
            float4 q2 = C_E2IH[(16 + u) * 8 + d];
            float4 q3 = C_E2IH[(24 + u) * 8 + d];
            float x0 = xin[4 * d + 0], x1 = xin[4 * d + 1];
            float x2 = xin[4 * d + 2], x3 = xin[4 * d + 3];
            a0 = fmaf(x0, q0.x, a0); a1 = fmaf(x0, q1.x, a1);
            a2 = fmaf(x0, q2.x, a2); a3 = fmaf(x0, q3.x, a3);
            a0 = fmaf(x1, q0.y, a0); a1 = fmaf(x1, q1.y, a1);
            a2 = fmaf(x1, q2.y, a2); a3 = fmaf(x1, q3.y, a3);
            a0 = fmaf(x2, q0.z, a0); a1 = fmaf(x2, q1.z, a1);
            a2 = fmaf(x2, q2.z, a2); a3 = fmaf(x2, q3.z, a3);
            a0 = fmaf(x3, q0.w, a0); a1 = fmaf(x3, q1.w, a1);
            a2 = fmaf(x3, q2.w, a2); a3 = fmaf(x3, q3.w, a3);
        }
        const float4* v0 = reinterpret_cast<const float4*>(swhh + u * 8);
        const float4* v1 = reinterpret_cast<const float4*>(swhh + (8 + u) * 8);
        const float4* v2 = reinterpret_cast<const float4*>(swhh + (16 + u) * 8);
        const float4* v3 = reinterpret_cast<const float4*>(swhh + (24 + u) * 8);
#pragma unroll
        for (int j = 0; j < 2; ++j) {
            float4 q0 = v0[j], q1 = v1[j], q2 = v2[j], q3 = v3[j];
            float h0 = h[4 * j + 0], h1v = h[4 * j + 1];
            float h2v = h[4 * j + 2], h3v = h[4 * j + 3];
            a0 = fmaf(h0, q0.x, a0); a1 = fmaf(h0, q1.x, a1);
            a2 = fmaf(h0, q2.x, a2); a3 = fmaf(h0, q3.x, a3);
            a0 = fmaf(h1v, q0.y, a0); a1 = fmaf(h1v, q1.y, a1);
            a2 = fmaf(h1v, q2.y, a2); a3 = fmaf(h1v, q3.y, a3);
            a0 = fmaf(h2v, q0.z, a0); a1 = fmaf(h2v, q1.z, a1);
            a2 = fmaf(h2v, q2.z, a2); a3 = fmaf(h2v, q3.z, a3);
            a0 = fmaf(h3v, q0.w, a0); a1 = fmaf(h3v, q1.w, a1);
            a2 = fmaf(h3v, q2.w, a2); a3 = fmaf(h3v, q3.w, a3);
        }
        float ig = sigf(a0);
        float fg = sigf(a1);
        float gg = tanhx(a2);
        float og = sigf(a3);
        float cn = fmaf(fg, c[u], ig * gg);
        c[u] = cn;
        hn[u] = og * tanhx(cn);
    }
#pragma unroll
    for (int u = 0; u < 8; ++u) h[u] = hn[u];
}

// Small scalar LSTM cell (smem weights), fully unrolled.
template<int H, int DIN>
__device__ __forceinline__ void lstm_small(
    const float* __restrict__ wih, const float* __restrict__ whh,
    const float* __restrict__ bias,
    const float (&xin)[DIN], float (&h)[H], float (&c)[H])
{
    float hn[H];
#pragma unroll
    for (int u = 0; u < H; ++u) {
        float a0 = bias[u];
        float a1 = bias[H + u];
        float a2 = bias[2 * H + u];
        float a3 = bias[3 * H + u];
#pragma unroll
        for (int d = 0; d < DIN; ++d) {
            float xv = xin[d];
            a0 = fmaf(xv, wih[u * DIN + d], a0);
            a1 = fmaf(xv, wih[(H + u) * DIN + d], a1);
            a2 = fmaf(xv, wih[(2 * H + u) * DIN + d], a2);
            a3 = fmaf(xv, wih[(3 * H + u) * DIN + d], a3);
        }
#pragma unroll
        for (int j = 0; j < H; ++j) {
            float hv = h[j];
            a0 = fmaf(hv, whh[u * H + j], a0);
            a1 = fmaf(hv, whh[(H + u) * H + j], a1);
            a2 = fmaf(hv, whh[(2 * H + u) * H + j], a2);
            a3 = fmaf(hv, whh[(3 * H + u) * H + j], a3);
        }
        float ig = sigf(a0);
        float fg = sigf(a1);
        float gg = tanhx(a2);
        float og = sigf(a3);
        float cn = fmaf(fg, c[u], ig * gg);
        c[u] = cn;
        hn[u] = og * tanhx(cn);
    }
#pragma unroll
    for (int u = 0; u < H; ++u) h[u] = hn[u];
}

__global__ void __launch_bounds__(TPB)
vd_encdec_kernel(
    const float* __restrict__ x,
    const float* __restrict__ w1ih, const float* __restrict__ w1hh,
    const float* __restrict__ w2hh,
    const float* __restrict__ w3ih, const float* __restrict__ w3hh, const float* __restrict__ b3,
    const float* __restrict__ d1ih, const float* __restrict__ d1hh, const float* __restrict__ bd1,
    const float* __restrict__ d2ih, const float* __restrict__ d2hh, const float* __restrict__ bd2,
    const float* __restrict__ d3ih, const float* __restrict__ d3hh, const float* __restrict__ bd3,
    const float* __restrict__ fc1w, const float* __restrict__ fc1b,
    const float* __restrict__ fc2w, const float* __restrict__ fc2b,
    float* __restrict__ out)
{
    __shared__ __align__(16) float sw[SMEM_FLOATS];
    const int tid = threadIdx.x;

    for (int i = tid; i < 1024; i += TPB) sw[OFF_W1IH + i] = w1ih[i];
    // rows 64..127 of w1hh (gates g,o)
    for (int i = tid; i < 2048; i += TPB) sw[OFF_W1HGO + i] = w1hh[64 * 32 + i];
    for (int i = tid; i < 256; i += TPB) sw[OFF_W2HH + i] = w2hh[i];
    for (int i = tid; i < 32; i += TPB) sw[OFF_W3IH + i] = w3ih[i];
    if (tid < 4)  sw[OFF_W3HH + tid] = w3hh[tid];
    if (tid < 4)  sw[OFF_B3   + tid] = b3[tid];
    if (tid < 8)  sw[OFF_D1IH + tid] = d1ih[tid];
    if (tid < 16) sw[OFF_D1HH + tid] = d1hh[tid];
    if (tid < 8)  sw[OFF_BD1 + tid] = bd1[tid];
    if (tid < 16) sw[OFF_D2IH + tid] = d2ih[tid];
    if (tid < 16) sw[OFF_D2HH + tid] = d2hh[tid];
    if (tid < 8)  sw[OFF_BD2 + tid] = bd2[tid];
    if (tid < 8)  sw[OFF_D3IH + tid] = d3ih[tid];
    if (tid < 4)  sw[OFF_D3HH + tid] = d3hh[tid];
    if (tid < 4)  sw[OFF_BD3 + tid] = bd3[tid];
    // fused fc: g[t*12+j] = sum_k fc2w[j,k] * fc1w[k,t]
    for (int i = tid; i < 720; i += TPB) {
        int t = i / 12, j = i % 12;
        float a = 0.0f;
        for (int k = 0; k < 32; ++k)
            a = fmaf(fc2w[j * 32 + k], fc1w[k * 60 + t], a);
        sw[OFF_G + i] = a;
    }
    if (tid < 12) {
        float a = fc2b[tid];
        for (int k = 0; k < 32; ++k)
            a = fmaf(fc2w[tid * 32 + k], fc1b[k], a);
        sw[OFF_CB + tid] = a;
    }
    __syncthreads();

    const int b = blockIdx.x * TPB + tid;
    const float* xb = x + (size_t)b * (T * 8);

    float h1[32], c1[32], h2[8], c2[8], h3[1], c3[1];
    float hd1[2], cd1[2], hd2[2], cd2[2], hd3[1], cd3[1];
    float acc[12];
#pragma unroll
    for (int i = 0; i < 32; ++i) { h1[i] = 0.0f; c1[i] = 0.0f; }
#pragma unroll
    for (int i = 0; i < 8; ++i) { h2[i] = 0.0f; c2[i] = 0.0f; }
    h3[0] = 0.0f; c3[0] = 0.0f;
#pragma unroll
    for (int i = 0; i < 2; ++i) { hd1[i] = 0.0f; cd1[i] = 0.0f; hd2[i] = 0.0f; cd2[i] = 0.0f; }
    hd3[0] = 0.0f; cd3[0] = 0.0f;
#pragma unroll
    for (int i = 0; i < 12; ++i) acc[i] = 0.0f;

    // ---- fused steps t = 0..47 ----
#pragma unroll 1
    for (int t = 0; t < T; ++t) {
        float4 xa = *reinterpret_cast<const float4*>(xb + t * 8);
        float4 xc = *reinterpret_cast<const float4*>(xb + t * 8 + 4);
        float xr[8] = { xa.x, xa.y, xa.z, xa.w, xc.x, xc.y, xc.z, xc.w };

        lstm_e1(sw + OFF_W1IH, sw + OFF_W1HGO, xr, h1, c1);
        lstm_e2(sw + OFF_W2HH, h1, h2, c2);
        lstm_small<1, 8>(sw + OFF_W3IH, sw + OFF_W3HH, sw + OFF_B3, h2, h3, c3);

        float dv[1] = { h3[0] };
        lstm_small<2, 1>(sw + OFF_D1IH, sw + OFF_D1HH, sw + OFF_BD1, dv, hd1, cd1);
        lstm_small<2, 2>(sw + OFF_D2IH, sw + OFF_D2HH, sw + OFF_BD2, hd1, hd2, cd2);
        lstm_small<1, 2>(sw + OFF_D3IH, sw + OFF_D3HH, sw + OFF_BD3, hd2, hd3, cd3);

        float y = hd3[0];
        const float* gr = sw + OFF_G + t * 12;
#pragma unroll
        for (int j = 0; j < 12; ++j) acc[j] = fmaf(y, gr[j], acc[j]);
    }

    // ---- aux steps t = 48..59: decoder input = x[b, t-12, 4] ----
#pragma unroll 1
    for (int t = T; t < 60; ++t) {
        float dv[1] = { xb[(t - 12) * 8 + 4] };
        lstm_small<2, 1>(sw + OFF_D1IH, sw + OFF_D1HH, sw + OFF_BD1, dv, hd1, cd1);
        lstm_small<2, 2>(sw + OFF_D2IH, sw + OFF_D2HH, sw + OFF_BD2, hd1, hd2, cd2);
        lstm_small<1, 2>(sw + OFF_D3IH, sw + OFF_D3HH, sw + OFF_BD3, hd2, hd3, cd3);

        float y = hd3[0];
        const float* gr = sw + OFF_G + t * 12;
#pragma unroll
        for (int j = 0; j < 12; ++j) acc[j] = fmaf(y, gr[j], acc[j]);
    }

    // ---- epilogue ----
    float r[12];
#pragma unroll
    for (int j = 0; j < 12; ++j) r[j] = acc[j] + sw[OFF_CB + j];
    float4* op = reinterpret_cast<float4*>(out + (size_t)b * 12);
    op[0] = make_float4(r[0], r[1], r[2], r[3]);
    op[1] = make_float4(r[4], r[5], r[6], r[7]);
    op[2] = make_float4(r[8], r[9], r[10], r[11]);
}

extern "C" void kernel_launch(void* const* d_in, const int* in_sizes, int n_in,
                              void* d_out, int out_size) {
    (void)in_sizes; (void)n_in; (void)out_size;
    const float* x    = (const float*)d_in[0];
    const float* w1ih = (const float*)d_in[1];
    const float* w1hh = (const float*)d_in[2];
    const float* b1   = (const float*)d_in[3];
    const float* w2ih = (const float*)d_in[4];
    const float* w2hh = (const float*)d_in[5];
    const float* b2   = (const float*)d_in[6];
    const float* w3ih = (const float*)d_in[7];
    const float* w3hh = (const float*)d_in[8];
    const float* b3   = (const float*)d_in[9];
    const float* d1ih = (const float*)d_in[10];
    const float* d1hh = (const float*)d_in[11];
    const float* bd1  = (const float*)d_in[12];
    const float* d2ih = (const float*)d_in[13];
    const float* d2hh = (const float*)d_in[14];
    const float* bd2  = (const float*)d_in[15];
    const float* d3ih = (const float*)d_in[16];
    const float* d3hh = (const float*)d_in[17];
    const float* bd3  = (const float*)d_in[18];
    const float* fc1w = (const float*)d_in[19];
    const float* fc1b = (const float*)d_in[20];
    const float* fc2w = (const float*)d_in[21];
    const float* fc2b = (const float*)d_in[22];
    float* out = (float*)d_out;

    // Stage const-port weights (D2D async, graph-capturable, no allocation).
    // C_E1HH_IF = rows 0..63 of w1hh (gates i,f): 64*32 floats
    cudaMemcpyToSymbolAsync(C_E1HH_IF, w1hh, 64 * 32 * 4, 0, cudaMemcpyDeviceToDevice, 0);
    // C_E2IH = full w2ih: 32*32 floats
    cudaMemcpyToSymbolAsync(C_E2IH, w2ih, 32 * 32 * 4, 0, cudaMemcpyDeviceToDevice, 0);
    cudaMemcpyToSymbolAsync(CB1, b1, 128 * 4, 0, cudaMemcpyDeviceToDevice, 0);
    cudaMemcpyToSymbolAsync(CB2, b2, 32 * 4, 0, cudaMemcpyDeviceToDevice, 0);

    dim3 grid(BATCH / TPB);
    dim3 block(TPB);
    vd_encdec_kernel<<<grid, block>>>(
        x, w1ih, w1hh, w2hh,
        w3ih, w3hh, b3,
        d1ih, d1hh, bd1, d2ih, d2hh, bd2, d3ih, d3hh, bd3,
        fc1w, fc1b, fc2w, fc2b, out);
}

// round 11
// speedup vs baseline: 1.2091x; 1.0261x over previous
#include <cuda_runtime.h>

// VDEncoderDecoder: stacked LSTM encoder (8->32->8->1, T=48) + decoder
// (1->2->2->1, 60 steps) + fused fc via g = fc2_w @ fc1_w.
// TWO warps per 32-element group: warp half h owns e1 units [16h,16h+16) and
// e2 units [4h,4h+4), computing all 4 gates for its 32 elements (lane =
// element). All weight loads warp-uniform (smem broadcast). New hidden state
// exchanged via smem + 2 __syncthreads per timestep. 2048 warps total
// (12/SM) vs 1024 before -> issue-rate, the measured binder, doubles.

#define TPB 64
static constexpr int BATCH = 32768;
static constexpr int T = 48;

// smem float offsets
static constexpr int OFF_W1IH = 0;       // 128x8   = 1024
static constexpr int OFF_W1HH = 1024;    // 128x32  = 4096
static constexpr int OFF_B1   = 5120;    // 128
static constexpr int OFF_W2IH = 5248;    // 32x32   = 1024
static constexpr int OFF_W2HH = 6272;    // 32x8    = 256
static constexpr int OFF_B2   = 6528;    // 32
static constexpr int OFF_W3IH = 6560;    // 32
static constexpr int OFF_W3HH = 6592;    // 4
static constexpr int OFF_B3   = 6596;    // 4
static constexpr int OFF_D1IH = 6600;    // 8
static constexpr int OFF_D1HH = 6608;    // 16
static constexpr int OFF_BD1  = 6624;    // 8
static constexpr int OFF_D2IH = 6632;    // 16
static constexpr int OFF_D2HH = 6648;    // 16
static constexpr int OFF_BD2  = 6664;    // 8
static constexpr int OFF_D3IH = 6672;    // 8
static constexpr int OFF_D3HH = 6680;    // 4
static constexpr int OFF_BD3  = 6684;    // 4
static constexpr int OFF_G    = 6688;    // 720
static constexpr int OFF_CB   = 7408;    // 12
static constexpr int OFF_H1B  = 7420;    // 32 units x 32 elems = 1024
static constexpr int OFF_H2B  = 8444;    // 8 units x 32 elems  = 256
static constexpr int SMEM_FLOATS = 8700; // 34.8 KB -> 6 CTAs/SM

__device__ __forceinline__ float sigf(float x) {
    return __fdividef(1.0f, 1.0f + __expf(-x));
}
__device__ __forceinline__ float tanhx(float x) {
    float e = __expf(2.0f * x);
    return 1.0f - __fdividef(2.0f, e + 1.0f);
}

// Small scalar LSTM cell (decoder path), fully unrolled.
template<int H, int DIN>
__device__ __forceinline__ void lstm_small(
    const float* __restrict__ wih, const float* __restrict__ whh,
    const float* __restrict__ bias,
    const float (&xin)[DIN], float (&h)[H], float (&c)[H])
{
    float hn[H];
#pragma unroll
    for (int u = 0; u < H; ++u) {
        float a0 = bias[u];
        float a1 = bias[H + u];
        float a2 = bias[2 * H + u];
        float a3 = bias[3 * H + u];
#pragma unroll
        for (int d = 0; d < DIN; ++d) {
            float xv = xin[d];
            a0 = fmaf(xv, wih[u * DIN + d], a0);
            a1 = fmaf(xv, wih[(H + u) * DIN + d], a1);
            a2 = fmaf(xv, wih[(2 * H + u) * DIN + d], a2);
            a3 = fmaf(xv, wih[(3 * H + u) * DIN + d], a3);
        }
#pragma unroll
        for (int j = 0; j < H; ++j) {
            float hv = h[j];
            a0 = fmaf(hv, whh[u * H + j], a0);
            a1 = fmaf(hv, whh[(H + u) * H + j], a1);
            a2 = fmaf(hv, whh[(2 * H + u) * H + j], a2);
            a3 = fmaf(hv, whh[(3 * H + u) * H + j], a3);
        }
        float ig = sigf(a0);
        float fg = sigf(a1);
        float gg = tanhx(a2);
        float og = sigf(a3);
        float cn = fmaf(fg, c[u], ig * gg);
        c[u] = cn;
        hn[u] = og * tanhx(cn);
    }
#pragma unroll
    for (int u = 0; u < H; ++u) h[u] = hn[u];
}

__global__ void __launch_bounds__(TPB, 6)
vd_encdec_kernel(
    const float* __restrict__ x,
    const float* __restrict__ w1ih, const float* __restrict__ w1hh, const float* __restrict__ b1,
    const float* __restrict__ w2ih, const float* __restrict__ w2hh, const float* __restrict__ b2,
    const float* __restrict__ w3ih, const float* __restrict__ w3hh, const float* __restrict__ b3,
    const float* __restrict__ d1ih, const float* __restrict__ d1hh, const float* __restrict__ bd1,
    const float* __restrict__ d2ih, const float* __restrict__ d2hh, const float* __restrict__ bd2,
    const float* __restrict__ d3ih, const float* __restrict__ d3hh, const float* __restrict__ bd3,
    const float* __restrict__ fc1w, const float* __restrict__ fc1b,
    const float* __restrict__ fc2w, const float* __restrict__ fc2b,
    float* __restrict__ out)
{
    __shared__ __align__(16) float sw[SMEM_FLOATS];
    const int tid = threadIdx.x;

    for (int i = tid; i < 1024; i += TPB) sw[OFF_W1IH + i] = w1ih[i];
    for (int i = tid; i < 4096; i += TPB) sw[OFF_W1HH + i] = w1hh[i];
    for (int i = tid; i < 128;  i += TPB) sw[OFF_B1   + i] = b1[i];
    for (int i = tid; i < 1024; i += TPB) sw[OFF_W2IH + i] = w2ih[i];
    for (int i = tid; i < 256;  i += TPB) sw[OFF_W2HH + i] = w2hh[i];
    for (int i = tid; i < 32;   i += TPB) sw[OFF_B2   + i] = b2[i];
    for (int i = tid; i < 32;   i += TPB) sw[OFF_W3IH + i] = w3ih[i];
    if (tid < 4)  sw[OFF_W3HH + tid] = w3hh[tid];
    if (tid < 4)  sw[OFF_B3   + tid] = b3[tid];
    if (tid < 8)  sw[OFF_D1IH + tid] = d1ih[tid];
    if (tid < 16) sw[OFF_D1HH + tid] = d1hh[tid];
    if (tid < 8)  sw[OFF_BD1 + tid] = bd1[tid];
    if (tid < 16) sw[OFF_D2IH + tid] = d2ih[tid];
    if (tid < 16) sw[OFF_D2HH + tid] = d2hh[tid];
    if (tid < 8)  sw[OFF_BD2 + tid] = bd2[tid];
    if (tid < 8)  sw[OFF_D3IH + tid] = d3ih[tid];
    if (tid < 4)  sw[OFF_D3HH + tid] = d3hh[tid];
    if (tid < 4)  sw[OFF_BD3 + tid] = bd3[tid];
    // fused fc: g[t*12+j] = sum_k fc2w[j,k] * fc1w[k,t]
    for (int i = tid; i < 720; i += TPB) {
        int t = i / 12, j = i % 12;
        float a = 0.0f;
        for (int k = 0; k < 32; ++k)
            a = fmaf(fc2w[j * 32 + k], fc1w[k * 60 + t], a);
        sw[OFF_G + i] = a;
    }
    if (tid < 12) {
        float a = fc2b[tid];
        for (int k = 0; k < 32; ++k)
            a = fmaf(fc2w[tid * 32 + k], fc1b[k], a);
        sw[OFF_CB + tid] = a;
    }
    __syncthreads();

    const int lane = tid & 31;
    const int half = tid >> 5;            // 0 or 1: which unit-half this warp owns
    const int elem = blockIdx.x * 32 + lane;
    const float* xe = x + (size_t)elem * (T * 8);
    const int ub1 = half * 16;            // my e1 units: ub1..ub1+15
    const int ub2 = half * 4;             // my e2 units: ub2..ub2+3

    float h1[32], h2[8];                  // FULL state (registers, static idx)
    float c1l[16], c2l[4];                // my units' c
    float h3[1], c3[1];
    float hd1[2], cd1[2], hd2[2], cd2[2], hd3[1], cd3[1];
    float acc[12];
#pragma unroll
    for (int i = 0; i < 32; ++i) h1[i] = 0.0f;
#pragma unroll
    for (int i = 0; i < 16; ++i) c1l[i] = 0.0f;
#pragma unroll
    for (int i = 0; i < 8; ++i) h2[i] = 0.0f;
#pragma unroll
    for (int i = 0; i < 4; ++i) c2l[i] = 0.0f;
    h3[0] = 0.0f; c3[0] = 0.0f;
#pragma unroll
    for (int i = 0; i < 2; ++i) { hd1[i] = 0.0f; cd1[i] = 0.0f; hd2[i] = 0.0f; cd2[i] = 0.0f; }
    hd3[0] = 0.0f; cd3[0] = 0.0f;
#pragma unroll
    for (int i = 0; i < 12; ++i) acc[i] = 0.0f;

    // ---- fused steps t = 0..47 ----
#pragma unroll 1
    for (int t = 0; t < T; ++t) {
        float4 xa = *reinterpret_cast<const float4*>(xe + t * 8);
        float4 xc = *reinterpret_cast<const float4*>(xe + t * 8 + 4);
        float xr[8] = { xa.x, xa.y, xa.z, xa.w, xc.x, xc.y, xc.z, xc.w };

        // ---- e1: my 16 units, all 4 gates ----
#pragma unroll 1
        for (int uu = 0; uu < 16; ++uu) {
            int u = ub1 + uu;
            float a0 = sw[OFF_B1 + u];
            float a1 = sw[OFF_B1 + 32 + u];
            float a2 = sw[OFF_B1 + 64 + u];
            float a3 = sw[OFF_B1 + 96 + u];
            const float4* w0 = reinterpret_cast<const float4*>(sw + OFF_W1IH + u * 8);
            const float4* w1 = reinterpret_cast<const float4*>(sw + OFF_W1IH + (32 + u) * 8);
            const float4* w2 = reinterpret_cast<const float4*>(sw + OFF_W1IH + (64 + u) * 8);
            const float4* w3 = reinterpret_cast<const float4*>(sw + OFF_W1IH + (96 + u) * 8);
#pragma unroll
            for (int d = 0; d < 2; ++d) {
                float4 q0 = w0[d], q1 = w1[d], q2 = w2[d], q3 = w3[d];
                float x0 = xr[4 * d + 0], x1 = xr[4 * d + 1];
                float x2 = xr[4 * d + 2], x3 = xr[4 * d + 3];
                a0 = fmaf(x0, q0.x, a0); a1 = fmaf(x0, q1.x, a1);
                a2 = fmaf(x0, q2.x, a2); a3 = fmaf(x0, q3.x, a3);
                a0 = fmaf(x1, q0.y, a0); a1 = fmaf(x1, q1.y, a1);
                a2 = fmaf(x1, q2.y, a2); a3 = fmaf(x1, q3.y, a3);
                a0 = fmaf(x2, q0.z, a0); a1 = fmaf(x2, q1.z, a1);
                a2 = fmaf(x2, q2.z, a2); a3 = fmaf(x2, q3.z, a3);
                a0 = fmaf(x3, q0.w, a0); a1 = fmaf(x3, q1.w, a1);
                a2 = fmaf(x3, q2.w, a2); a3 = fmaf(x3, q3.w, a3);
            }
            const float4* v0 = reinterpret_cast<const float4*>(sw + OFF_W1HH + u * 32);
            const float4* v1 = reinterpret_cast<const float4*>(sw + OFF_W1HH + (32 + u) * 32);
            const float4* v2 = reinterpret_cast<const float4*>(sw + OFF_W1HH + (64 + u) * 32);
            const float4* v3 = reinterpret_cast<const float4*>(sw + OFF_W1HH + (96 + u) * 32);
#pragma unroll
            for (int j = 0; j < 8; ++j) {
                float4 q0 = v0[j], q1 = v1[j], q2 = v2[j], q3 = v3[j];
                float p0 = h1[4 * j + 0], p1 = h1[4 * j + 1];
                float p2 = h1[4 * j + 2], p3 = h1[4 * j + 3];
                a0 = fmaf(p0, q0.x, a0); a1 = fmaf(p0, q1.x, a1);
                a2 = fmaf(p0, q2.x, a2); a3 = fmaf(p0, q3.x, a3);
                a0 = fmaf(p1, q0.y, a0); a1 = fmaf(p1, q1.y, a1);
                a2 = fmaf(p1, q2.y, a2); a3 = fmaf(p1, q3.y, a3);
                a0 = fmaf(p2, q0.z, a0); a1 = fmaf(p2, q1.z, a1);
                a2 = fmaf(p2, q2.z, a2); a3 = fmaf(p2, q3.z, a3);
                a0 = fmaf(p3, q0.w, a0); a1 = fmaf(p3, q1.w, a1);
                a2 = fmaf(p3, q2.w, a2); a3 = fmaf(p3, q3.w, a3);
            }
            float ig = sigf(a0);
            float fg = sigf(a1);
            float gg = tanhx(a2);
            float og = sigf(a3);
            float cn = fmaf(fg, c1l[uu], ig * gg);
            c1l[uu] = cn;
            sw[OFF_H1B + u * 32 + lane] = og * tanhx(cn);
        }
        __syncthreads();   // new h1 visible to both halves
#pragma unroll
        for (int j = 0; j < 32; ++j) h1[j] = sw[OFF_H1B + j * 32 + lane];

        // ---- e2: my 4 units ----
#pragma unroll 1
        for (int uu = 0; uu < 4; ++uu) {
            int u = ub2 + uu;
            float a0 = sw[OFF_B2 + u];
            float a1 = sw[OFF_B2 + 8 + u];
            float a2 = sw[OFF_B2 + 16 + u];
            float a3 = sw[OFF_B2 + 24 + u];
            const float4* w0 = reinterpret_cast<const float4*>(sw + OFF_W2IH + u * 32);
            const float4* w1 = reinterpret_cast<const float4*>(sw + OFF_W2IH + (8 + u) * 32);
            const float4* w2 = reinterpret_cast<const float4*>(sw + OFF_W2IH + (16 + u) * 32);
            const float4* w3 = reinterpret_cast<const float4*>(sw + OFF_W2IH + (24 + u) * 32);
#pragma unroll
            for (int d = 0; d < 8; ++d) {
                float4 q0 = w0[d], q1 = w1[d], q2 = w2[d], q3 = w3[d];
                float p0 = h1[4 * d + 0], p1 = h1[4 * d + 1];
                float p2 = h1[4 * d + 2], p3 = h1[4 * d + 3];
                a0 = fmaf(p0, q0.x, a0); a1 = fmaf(p0, q1.x, a1);
                a2 = fmaf(p0, q2.x, a2); a3 = fmaf(p0, q3.x, a3);
                a0 = fmaf(p1, q0.y, a0); a1 = fmaf(p1, q1.y, a1);
                a2 = fmaf(p1, q2.y, a2); a3 = fmaf(p1, q3.y, a3);
                a0 = fmaf(p2, q0.z, a0); a1 = fmaf(p2, q1.z, a1);
                a2 = fmaf(p2, q2.z, a2); a3 = fmaf(p2, q3.z, a3);
                a0 = fmaf(p3, q0.w, a0); a1 = fmaf(p3, q1.w, a1);
                a2 = fmaf(p3, q2.w, a2); a3 = fmaf(p3, q3.w, a3);
            }
            const float4* v0 = reinterpret_cast<const float4*>(sw + OFF_W2HH + u * 8);
            const float4* v1 = reinterpret_cast<const float4*>(sw + OFF_W2HH + (8 + u) * 8);
            const float4* v2 = reinterpret_cast<const float4*>(sw + OFF_W2HH + (16 + u) * 8);
            const float4* v3 = reinterpret_cast<const float4*>(sw + OFF_W2HH + (24 + u) * 8);
#pragma unroll
            for (int j = 0; j < 2; ++j) {
                float4 q0 = v0[j], q1 = v1[j], q2 = v2[j], q3 = v3[j];
                float p0 = h2[4 * j + 0], p1 = h2[4 * j + 1];
                float p2 = h2[4 * j + 2], p3 = h2[4 * j + 3];
                a0 = fmaf(p0, q0.x, a0); a1 = fmaf(p0, q1.x, a1);
                a2 = fmaf(p0, q2.x, a2); a3 = fmaf(p0, q3.x, a3);
                a0 = fmaf(p1, q0.y, a0); a1 = fmaf(p1, q1.y, a1);
                a2 = fmaf(p1, q2.y, a2); a3 = fmaf(p1, q3.y, a3);
                a0 = fmaf(p2, q0.z, a0); a1 = fmaf(p2, q1.z, a1);
                a2 = fmaf(p2, q2.z, a2); a3 = fmaf(p2, q3.z, a3);
                a0 = fmaf(p3, q0.w, a0); a1 = fmaf(p3, q1.w, a1);
                a2 = fmaf(p3, q2.w, a2); a3 = fmaf(p3, q3.w, a3);
            }
            float ig = sigf(a0);
            float fg = sigf(a1);
            float gg = tanhx(a2);
            float og = sigf(a3);
            float cn = fmaf(fg, c2l[uu], ig * gg);
            c2l[uu] = cn;
            sw[OFF_H2B + u * 32 + lane] = og * tanhx(cn);
        }
        __syncthreads();   // new h2 visible
#pragma unroll
        for (int j = 0; j < 8; ++j) h2[j] = sw[OFF_H2B + j * 32 + lane];

        // ---- e3 + decoder + fc on half 0 only (warp-uniform branch) ----
        if (half == 0) {
            lstm_small<1, 8>(sw + OFF_W3IH, sw + OFF_W3HH, sw + OFF_B3, h2, h3, c3);
            float dv[1] = { h3[0] };
            lstm_small<2, 1>(sw + OFF_D1IH, sw + OFF_D1HH, sw + OFF_BD1, dv, hd1, cd1);
            lstm_small<2, 2>(sw + OFF_D2IH, sw + OFF_D2HH, sw + OFF_BD2, hd1, hd2, cd2);
            lstm_small<1, 2>(sw + OFF_D3IH, sw + OFF_D3HH, sw + OFF_BD3, hd2, hd3, cd3);
            float y = hd3[0];
            const float* gr = sw + OFF_G + t * 12;
#pragma unroll
            for (int j = 0; j < 12; ++j) acc[j] = fmaf(y, gr[j], acc[j]);
        }
    }

    // ---- aux steps + epilogue: half 0 only (no syncs below) ----
    if (half == 0) {
#pragma unroll 1
        for (int t = T; t < 60; ++t) {
            float dv[1] = { xe[(t - 12) * 8 + 4] };
            lstm_small<2, 1>(sw + OFF_D1IH, sw + OFF_D1HH, sw + OFF_BD1, dv, hd1, cd1);
            lstm_small<2, 2>(sw + OFF_D2IH, sw + OFF_D2HH, sw + OFF_BD2, hd1, hd2, cd2);
            lstm_small<1, 2>(sw + OFF_D3IH, sw + OFF_D3HH, sw + OFF_BD3, hd2, hd3, cd3);
            float y = hd3[0];
            const float* gr = sw + OFF_G + t * 12;
#pragma unroll
            for (int j = 0; j < 12; ++j) acc[j] = fmaf(y, gr[j], acc[j]);
        }
        float r[12];
#pragma unroll
        for (int j = 0; j < 12; ++j) r[j] = acc[j] + sw[OFF_CB + j];
        float4* op = reinterpret_cast<float4*>(out + (size_t)elem * 12);
        op[0] = make_float4(r[0], r[1], r[2], r[3]);
        op[1] = make_float4(r[4], r[5], r[6], r[7]);
        op[2] = make_float4(r[8], r[9], r[10], r[11]);
    }
}

extern "C" void kernel_launch(void* const* d_in, const int* in_sizes, int n_in,
                              void* d_out, int out_size) {
    (void)in_sizes; (void)n_in; (void)out_size;
    const float* x    = (const float*)d_in[0];
    const float* w1ih = (const float*)d_in[1];
    const float* w1hh = (const float*)d_in[2];
    const float* b1   = (const float*)d_in[3];
    const float* w2ih = (const float*)d_in[4];
    const float* w2hh = (const float*)d_in[5];
    const float* b2   = (const float*)d_in[6];
    const float* w3ih = (const float*)d_in[7];
    const float* w3hh = (const float*)d_in[8];
    const float* b3   = (const float*)d_in[9];
    const float* d1ih = (const float*)d_in[10];
    const float* d1hh = (const float*)d_in[11];
    const float* bd1  = (const float*)d_in[12];
    const float* d2ih = (const float*)d_in[13];
    const float* d2hh = (const float*)d_in[14];
    const float* bd2  = (const float*)d_in[15];
    const float* d3ih = (const float*)d_in[16];
    const float* d3hh = (const float*)d_in[17];
    const float* bd3  = (const float*)d_in[18];
    const float* fc1w = (const float*)d_in[19];
    const float* fc1b = (const float*)d_in[20];
    const float* fc2w = (const float*)d_in[21];
    const float* fc2b = (const float*)d_in[22];
    float* out = (float*)d_out;

    dim3 grid(BATCH / 32);   // one 32-element group (2 warps) per CTA
    dim3 block(TPB);
    vd_encdec_kernel<<<grid, block>>>(
        x, w1ih, w1hh, b1, w2ih, w2hh, b2, w3ih, w3hh, b3,
        d1ih, d1hh, bd1, d2ih, d2hh, bd2, d3ih, d3hh, bd3,
        fc1w, fc1b, fc2w, fc2b, out);
}